// round 12
// baseline (speedup 1.0000x reference)
#include <cuda_runtime.h>
#include <math.h>
#include <stdint.h>

#define BB   8
#define NN   2048
#define FIN  512
#define FOUT 256

__device__ float g_h[(size_t)BB * NN * FOUT];   // tf32-prerounded h
__device__ float g_f[BB * NN];
__device__ float g_g[BB * NN];

__device__ __forceinline__ uint32_t to_tf32(float f) {
    uint32_t r; asm("cvt.rna.tf32.f32 %0, %1;" : "=r"(r) : "f"(f)); return r;
}
__device__ __forceinline__ void mma_tf32(float* d, const uint32_t* a, const uint32_t* b) {
    asm volatile(
        "mma.sync.aligned.m16n8k8.row.col.f32.tf32.tf32.f32 "
        "{%0,%1,%2,%3}, {%4,%5,%6,%7}, {%8,%9}, {%0,%1,%2,%3};"
        : "+f"(d[0]), "+f"(d[1]), "+f"(d[2]), "+f"(d[3])
        : "r"(a[0]), "r"(a[1]), "r"(a[2]), "r"(a[3]), "r"(b[0]), "r"(b[1]));
}
__device__ __forceinline__ uint32_t smem_u32(const void* p) {
    uint32_t a;
    asm("{ .reg .u64 t; cvta.to.shared.u64 t, %1; cvt.u32.u64 %0, t; }" : "=r"(a) : "l"(p));
    return a;
}
__device__ __forceinline__ void cp16(uint32_t dst, const void* src) {
    asm volatile("cp.async.cg.shared.global [%0], [%1], 16;" :: "r"(dst), "l"(src));
}
#define CP_COMMIT() asm volatile("cp.async.commit_group;" ::: "memory")
#define CP_WAIT0()  asm volatile("cp.async.wait_group 0;" ::: "memory")

// ===========================================================================
// Kernel 1: h = x @ W via split-tf32 mma (3 MMAs) + fused f/g.
// k-step 32 per iteration (16 iterations) to halve barrier/convoy overhead.
// 128 blocks x 512 threads.
// smem floats: xs[2][128*36]@0 | ws[2][32*264]@18432   (104.4 KB)
// ===========================================================================
#define XS_OFF 0
#define XS_SZ  4608
#define WS_OFF 9216
#define WS_SZ  8448
#define GH_SMEM ((9216 + 16896) * 4)

__global__ __launch_bounds__(512, 1)
void gemm_h_kernel(const float* __restrict__ x, const float* __restrict__ W,
                   const float* __restrict__ a)
{
    extern __shared__ float sm[];
    const uint32_t sb = smem_u32(sm);

    const int t    = threadIdx.x;
    const int m0   = blockIdx.x * 128;
    const int warp = t >> 5, lane = t & 31;
    const int g    = lane >> 2, tig = lane & 3;
    const int wi   = warp >> 2, wo = warp & 3;

    // loaders: x tile 128x32 (2 cp16/thread), W tile 32x256 (4 cp16/thread)
    const int xrow = t >> 2, xseg = (t & 3) * 8;
    const int wrow = t >> 4, wseg = (t & 15) * 16;
    const float* xsrc = x + (size_t)(m0 + xrow) * FIN + xseg;
    const float* wsrc = W + (size_t)wrow * FOUT + wseg;

    auto issue = [&](int s) {
        uint32_t xd = sb + (XS_OFF + (s & 1) * XS_SZ + xrow * 36 + xseg) * 4;
        cp16(xd,      xsrc + s * 32);
        cp16(xd + 16, xsrc + s * 32 + 4);
        uint32_t wd = sb + (WS_OFF + (s & 1) * WS_SZ + wrow * 264 + wseg) * 4;
        const float* wsr = wsrc + (size_t)s * 32 * FOUT;
        cp16(wd,      wsr);
        cp16(wd + 16, wsr + 4);
        cp16(wd + 32, wsr + 8);
        cp16(wd + 48, wsr + 12);
        CP_COMMIT();
    };

    float acc[2][8][4];
    #pragma unroll
    for (int ma = 0; ma < 2; ma++)
        #pragma unroll
        for (int na = 0; na < 8; na++)
            #pragma unroll
            for (int c = 0; c < 4; c++) acc[ma][na][c] = 0.f;

    issue(0);
    CP_WAIT0();
    __syncthreads();

    for (int s = 0; s < 16; s++) {
        if (s < 15) issue(s + 1);
        const float* xs = sm + XS_OFF + (s & 1) * XS_SZ;
        const float* ws = sm + WS_OFF + (s & 1) * WS_SZ;

        #pragma unroll
        for (int ks = 0; ks < 4; ks++) {
            uint32_t bhi[8][2], blo[8][2];
            #pragma unroll
            for (int na = 0; na < 8; na++) {
                int o = wo * 64 + na * 8 + g;
                float r0 = ws[(ks * 8 + tig) * 264 + o];
                float r1 = ws[(ks * 8 + tig + 4) * 264 + o];
                bhi[na][0] = to_tf32(r0);
                blo[na][0] = to_tf32(r0 - __uint_as_float(bhi[na][0]));
                bhi[na][1] = to_tf32(r1);
                blo[na][1] = to_tf32(r1 - __uint_as_float(bhi[na][1]));
            }
            #pragma unroll
            for (int ma = 0; ma < 2; ma++) {
                int R = wi * 32 + ma * 16;
                float r0 = xs[(R + g) * 36 + ks * 8 + tig];
                float r1 = xs[(R + g + 8) * 36 + ks * 8 + tig];
                float r2 = xs[(R + g) * 36 + ks * 8 + tig + 4];
                float r3 = xs[(R + g + 8) * 36 + ks * 8 + tig + 4];
                uint32_t ahi[4], alo[4];
                ahi[0] = to_tf32(r0); alo[0] = to_tf32(r0 - __uint_as_float(ahi[0]));
                ahi[1] = to_tf32(r1); alo[1] = to_tf32(r1 - __uint_as_float(ahi[1]));
                ahi[2] = to_tf32(r2); alo[2] = to_tf32(r2 - __uint_as_float(ahi[2]));
                ahi[3] = to_tf32(r3); alo[3] = to_tf32(r3 - __uint_as_float(ahi[3]));
                #pragma unroll
                for (int na = 0; na < 8; na++) {
                    mma_tf32(acc[ma][na], ahi, bhi[na]);
                    mma_tf32(acc[ma][na], alo, bhi[na]);
                    mma_tf32(acc[ma][na], ahi, blo[na]);
                }
            }
        }
        if (s < 15) CP_WAIT0();
        __syncthreads();
    }

    float a1c[16], a2c[16];
    #pragma unroll
    for (int na = 0; na < 8; na++) {
        int col = wo * 64 + na * 8 + tig * 2;
        a1c[2*na]   = __ldg(a + col);
        a1c[2*na+1] = __ldg(a + col + 1);
        a2c[2*na]   = __ldg(a + FOUT + col);
        a2c[2*na+1] = __ldg(a + FOUT + col + 1);
    }
    float* fred = sm;
    float* gred = sm + 512;

    #pragma unroll
    for (int ma = 0; ma < 2; ma++) {
        int ra = wi * 32 + ma * 16 + g;
        int rb = ra + 8;
        float fA = 0.f, gA = 0.f, fB = 0.f, gB = 0.f;
        #pragma unroll
        for (int na = 0; na < 8; na++) {
            int col = wo * 64 + na * 8 + tig * 2;
            float c0 = acc[ma][na][0], c1 = acc[ma][na][1];
            float c2 = acc[ma][na][2], c3 = acc[ma][na][3];
            float2 sA = make_float2(__uint_as_float(to_tf32(c0)), __uint_as_float(to_tf32(c1)));
            float2 sB = make_float2(__uint_as_float(to_tf32(c2)), __uint_as_float(to_tf32(c3)));
            *(float2*)(g_h + (size_t)(m0 + ra) * FOUT + col) = sA;
            *(float2*)(g_h + (size_t)(m0 + rb) * FOUT + col) = sB;
            fA += c0 * a1c[2*na] + c1 * a1c[2*na+1];
            gA += c0 * a2c[2*na] + c1 * a2c[2*na+1];
            fB += c2 * a1c[2*na] + c3 * a1c[2*na+1];
            gB += c2 * a2c[2*na] + c3 * a2c[2*na+1];
        }
        fA += __shfl_xor_sync(0xffffffffu, fA, 1); fA += __shfl_xor_sync(0xffffffffu, fA, 2);
        gA += __shfl_xor_sync(0xffffffffu, gA, 1); gA += __shfl_xor_sync(0xffffffffu, gA, 2);
        fB += __shfl_xor_sync(0xffffffffu, fB, 1); fB += __shfl_xor_sync(0xffffffffu, fB, 2);
        gB += __shfl_xor_sync(0xffffffffu, gB, 1); gB += __shfl_xor_sync(0xffffffffu, gB, 2);
        if (tig == 0) {
            fred[wo * 128 + ra] = fA; fred[wo * 128 + rb] = fB;
            gred[wo * 128 + ra] = gA; gred[wo * 128 + rb] = gB;
        }
    }
    __syncthreads();
    if (t < 128) {
        float fv = fred[t] + fred[128 + t] + fred[256 + t] + fred[384 + t];
        float gv = gred[t] + gred[128 + t] + gred[256 + t] + gred[384 + t];
        g_f[m0 + t] = fv;
        g_g[m0 + t] = gv;
    }
}

// ===========================================================================
// Kernel 2: attention, mma.sync tf32, 1024 threads, warp grid 4(i) x 8(o).
// j-tile 64 per iteration (32 iterations): halves barrier/convoy overhead,
// doubles the independent LDS+MMA window per phase.
// smem floats: dsum[1024]@0 | gs[2048]@1024 | ps[2][128*68]@3072 | hs[2][64*264]@20480
// total = 54272 floats = 217 KB
// ===========================================================================
#define AT_DSUM 0
#define AT_GS   1024
#define AT_PS0  3072
#define AT_PS1  11776
#define AT_HS0  20480
#define AT_HS1  37376
#define ATTN_SMEM (54272 * 4)

__global__ __launch_bounds__(1024, 1)
void attn_kernel(const int* __restrict__ adj, float* __restrict__ out)
{
    extern __shared__ float smf[];
    const uint32_t sb = smem_u32(smf);

    const int t    = threadIdx.x;
    const int b    = blockIdx.x >> 4;
    const int i0   = (blockIdx.x & 15) << 7;
    const int warp = t >> 5, lane = t & 31;
    const int g    = lane >> 2, tig = lane & 3;
    const int wiq  = warp >> 3, wo = warp & 7;   // wiq 0..3 (i), wo 0..7 (o)

    // producer roles: 8 threads per p-row, 8 j each
    const int irow = t >> 3;        // 0..127
    const int jq   = t & 7;         // j-eighth of 64 (8 each)
    const int hjr  = t >> 4;        // 0..63 (h row)
    const int hoc  = (t & 15) * 16; // h col base (16 floats = 4 cp16)

    for (int j = t; j < NN; j += 1024) smf[AT_GS + j] = g_g[b * NN + j];
    const float fv = g_f[b * NN + i0 + irow];
    const int*   adjrow = adj + ((size_t)b * NN + i0 + irow) * NN + jq * 8;
    const float* hb     = g_h + (size_t)b * NN * FOUT;

    float acc[2][4][4];
    #pragma unroll
    for (int ma = 0; ma < 2; ma++)
        #pragma unroll
        for (int na = 0; na < 4; na++)
            #pragma unroll
            for (int c = 0; c < 4; c++) acc[ma][na][c] = 0.f;
    float dloc = 0.f;

    auto cp_h = [&](int jt) {
        const float* src = hb + (size_t)(jt * 64 + hjr) * FOUT + hoc;
        uint32_t dst = sb + (AT_HS0 + (jt & 1) * (AT_HS1 - AT_HS0) + hjr * 264 + hoc) * 4;
        cp16(dst,      src);
        cp16(dst + 16, src + 4);
        cp16(dst + 32, src + 8);
        cp16(dst + 48, src + 12);
        CP_COMMIT();
    };
    auto ld_adj = [&](int jtp, int4* av) {
        av[0] = *(const int4*)(adjrow + jtp * 64);
        av[1] = *(const int4*)(adjrow + jtp * 64 + 4);
    };
    auto store_p = [&](int jtp, const int4* av) {
        float* ps = smf + (jtp & 1 ? AT_PS1 : AT_PS0) + irow * 68 + jq * 8;
        const float* gsr = smf + AT_GS + jtp * 64 + jq * 8;
        #pragma unroll
        for (int q = 0; q < 2; q++) {
            int4 v = av[q];
            float z0 = fv + gsr[4*q+0]; z0 = z0 >= 0.f ? z0 : 0.2f * z0;
            float z1 = fv + gsr[4*q+1]; z1 = z1 >= 0.f ? z1 : 0.2f * z1;
            float z2 = fv + gsr[4*q+2]; z2 = z2 >= 0.f ? z2 : 0.2f * z2;
            float z3 = fv + gsr[4*q+3]; z3 = z3 >= 0.f ? z3 : 0.2f * z3;
            float p0 = (v.x > 0) ? __expf(z0) : 0.f;
            float p1 = (v.y > 0) ? __expf(z1) : 0.f;
            float p2 = (v.z > 0) ? __expf(z2) : 0.f;
            float p3 = (v.w > 0) ? __expf(z3) : 0.f;
            dloc += p0 + p1 + p2 + p3;
            float4 st = make_float4(__uint_as_float(to_tf32(p0)),
                                    __uint_as_float(to_tf32(p1)),
                                    __uint_as_float(to_tf32(p2)),
                                    __uint_as_float(to_tf32(p3)));
            *(float4*)(ps + 4 * q) = st;
        }
    };
    auto do_mma = [&](int jt) {
        const uint32_t* psu = (const uint32_t*)(smf + (jt & 1 ? AT_PS1 : AT_PS0));
        const uint32_t* hsu = (const uint32_t*)(smf + (jt & 1 ? AT_HS1 : AT_HS0));
        #pragma unroll
        for (int ks = 0; ks < 8; ks++) {
            uint32_t afr[2][4];
            #pragma unroll
            for (int ma = 0; ma < 2; ma++) {
                int base = (wiq * 32 + ma * 16 + g) * 68 + ks * 8 + tig;
                afr[ma][0] = psu[base];
                afr[ma][1] = psu[base + 8 * 68];
                afr[ma][2] = psu[base + 4];
                afr[ma][3] = psu[base + 8 * 68 + 4];
            }
            uint32_t bfr[4][2];
            #pragma unroll
            for (int na = 0; na < 4; na++) {
                int o = wo * 32 + na * 8 + g;
                bfr[na][0] = hsu[(ks * 8 + tig) * 264 + o];
                bfr[na][1] = hsu[(ks * 8 + tig + 4) * 264 + o];
            }
            #pragma unroll
            for (int ma = 0; ma < 2; ma++)
                #pragma unroll
                for (int na = 0; na < 4; na++)
                    mma_tf32(acc[ma][na], afr[ma], bfr[na]);
        }
    };

    // ---- prologue ----
    int4 A0[2];
    cp_h(0);
    ld_adj(0, A0);
    CP_WAIT0();
    __syncthreads();
    store_p(0, A0);
    ld_adj(1, A0);
    __syncthreads();

    // ---- main loop: 32 iterations ----
    for (int jt = 0; jt < 32; jt++) {
        if (jt < 31) cp_h(jt + 1);
        do_mma(jt);
        if (jt < 31) {
            store_p(jt + 1, A0);
            if (jt + 2 < 32) ld_adj(jt + 2, A0);
            CP_WAIT0();
        }
        __syncthreads();
    }

    smf[AT_DSUM + jq * 128 + irow] = dloc;
    __syncthreads();

    #pragma unroll
    for (int ma = 0; ma < 2; ma++) {
        int ra = wiq * 32 + ma * 16 + g;
        int rb = ra + 8;
        float da = 0.f, db = 0.f;
        #pragma unroll
        for (int s = 0; s < 8; s++) {
            da += smf[AT_DSUM + s * 128 + ra];
            db += smf[AT_DSUM + s * 128 + rb];
        }
        float inva = (da > 0.f) ? 1.f / da : 0.f;
        float invb = (db > 0.f) ? 1.f / db : 0.f;
        float* outa = out + ((size_t)b * NN + i0 + ra) * FOUT;
        float* outb = out + ((size_t)b * NN + i0 + rb) * FOUT;
        #pragma unroll
        for (int na = 0; na < 4; na++) {
            int col = wo * 32 + na * 8 + tig * 2;
            float v0 = acc[ma][na][0] * inva;
            float v1 = acc[ma][na][1] * inva;
            float v2 = acc[ma][na][2] * invb;
            float v3 = acc[ma][na][3] * invb;
            v0 = v0 > 0.f ? v0 : expm1f(v0);
            v1 = v1 > 0.f ? v1 : expm1f(v1);
            v2 = v2 > 0.f ? v2 : expm1f(v2);
            v3 = v3 > 0.f ? v3 : expm1f(v3);
            *(float2*)(outa + col) = make_float2(v0, v1);
            *(float2*)(outb + col) = make_float2(v2, v3);
        }
    }
}

// ---------------------------------------------------------------------------
extern "C" void kernel_launch(void* const* d_in, const int* in_sizes, int n_in,
                              void* d_out, int out_size)
{
    const float* x   = (const float*)d_in[0];
    const int*   adj = (const int*)d_in[1];
    const float* W   = (const float*)d_in[2];
    const float* a   = (const float*)d_in[3];
    float*       out = (float*)d_out;

    cudaFuncSetAttribute(gemm_h_kernel, cudaFuncAttributeMaxDynamicSharedMemorySize, GH_SMEM);
    cudaFuncSetAttribute(attn_kernel,   cudaFuncAttributeMaxDynamicSharedMemorySize, ATTN_SMEM);

    gemm_h_kernel<<<128, 512, GH_SMEM>>>(x, W, a);
    attn_kernel<<<128, 1024, ATTN_SMEM>>>(adj, out);
}

// round 13
// speedup vs baseline: 1.2652x; 1.2652x over previous
#include <cuda_runtime.h>
#include <math.h>
#include <stdint.h>

#define BB   8
#define NN   2048
#define FIN  512
#define FOUT 256

__device__ float g_h[(size_t)BB * NN * FOUT];   // tf32-prerounded h
__device__ float g_f[BB * NN];
__device__ float g_g[BB * NN];
__device__ float g_w12[2 * FIN];                // w1 = W@a1, w2 = W@a2

__device__ __forceinline__ uint32_t to_tf32(float f) {
    uint32_t r; asm("cvt.rna.tf32.f32 %0, %1;" : "=r"(r) : "f"(f)); return r;
}
__device__ __forceinline__ void mma_tf32(float* d, const uint32_t* a, const uint32_t* b) {
    asm volatile(
        "mma.sync.aligned.m16n8k8.row.col.f32.tf32.tf32.f32 "
        "{%0,%1,%2,%3}, {%4,%5,%6,%7}, {%8,%9}, {%0,%1,%2,%3};"
        : "+f"(d[0]), "+f"(d[1]), "+f"(d[2]), "+f"(d[3])
        : "r"(a[0]), "r"(a[1]), "r"(a[2]), "r"(a[3]), "r"(b[0]), "r"(b[1]));
}
__device__ __forceinline__ uint32_t smem_u32(const void* p) {
    uint32_t a;
    asm("{ .reg .u64 t; cvta.to.shared.u64 t, %1; cvt.u32.u64 %0, t; }" : "=r"(a) : "l"(p));
    return a;
}
__device__ __forceinline__ void cp16(uint32_t dst, const void* src) {
    asm volatile("cp.async.cg.shared.global [%0], [%1], 16;" :: "r"(dst), "l"(src));
}
#define CP_COMMIT() asm volatile("cp.async.commit_group;" ::: "memory")
#define CP_WAIT0()  asm volatile("cp.async.wait_group 0;" ::: "memory")

// ===========================================================================
// Kernel 0: w1 = W @ a1, w2 = W @ a2 (fp32). 64 blocks x 256 threads,
// one warp per k-row.
// ===========================================================================
__global__ __launch_bounds__(256, 1)
void wv_kernel(const float* __restrict__ W, const float* __restrict__ a)
{
    const int warp = threadIdx.x >> 5, lane = threadIdx.x & 31;
    const int k = blockIdx.x * 8 + warp;
    const float* wr = W + (size_t)k * FOUT;
    float s1 = 0.f, s2 = 0.f;
    #pragma unroll
    for (int q = 0; q < 2; q++) {
        float4 wv = *(const float4*)(wr + lane * 8 + q * 4);
        float4 a1 = *(const float4*)(a + lane * 8 + q * 4);
        float4 a2 = *(const float4*)(a + FOUT + lane * 8 + q * 4);
        s1 += wv.x * a1.x + wv.y * a1.y + wv.z * a1.z + wv.w * a1.w;
        s2 += wv.x * a2.x + wv.y * a2.y + wv.z * a2.z + wv.w * a2.w;
    }
    #pragma unroll
    for (int d = 16; d >= 1; d >>= 1) {
        s1 += __shfl_xor_sync(0xffffffffu, s1, d);
        s2 += __shfl_xor_sync(0xffffffffu, s2, d);
    }
    if (lane == 0) { g_w12[k] = s1; g_w12[FIN + k] = s2; }
}

// ===========================================================================
// Kernel 2 (after gemm_h): f = x @ w1, g = x @ w2 (fp32 FFMA, HBM-bound).
// 2048 blocks x 256 threads, one warp per row.
// ===========================================================================
__global__ __launch_bounds__(256, 1)
void fg_kernel(const float* __restrict__ x)
{
    const int warp = threadIdx.x >> 5, lane = threadIdx.x & 31;
    const int row = blockIdx.x * 8 + warp;
    const float* xr = x + (size_t)row * FIN;
    float f = 0.f, g = 0.f;
    #pragma unroll
    for (int q = 0; q < 4; q++) {
        float4 v  = *(const float4*)(xr + lane * 4 + q * 128);
        float4 w1 = *(const float4*)(g_w12 + lane * 4 + q * 128);
        float4 w2 = *(const float4*)(g_w12 + FIN + lane * 4 + q * 128);
        f += v.x * w1.x + v.y * w1.y + v.z * w1.z + v.w * w1.w;
        g += v.x * w2.x + v.y * w2.y + v.z * w2.z + v.w * w2.w;
    }
    #pragma unroll
    for (int d = 16; d >= 1; d >>= 1) {
        f += __shfl_xor_sync(0xffffffffu, f, d);
        g += __shfl_xor_sync(0xffffffffu, g, d);
    }
    if (lane == 0) { g_f[row] = f; g_g[row] = g; }
}

// ===========================================================================
// Kernel 1: h = x @ W, SINGLE tf32 MMA (numerator-grade accuracy).
// 128 blocks x 512 threads, k-step 16, 32 iterations. h stored tf32-rounded.
// smem floats: xs[2][128*20]@0 | ws[2][16*264]@5120
// ===========================================================================
#define XS_OFF 0
#define XS_SZ  2560
#define WS_OFF 5120
#define WS_SZ  4224
#define GH_SMEM 54272

__global__ __launch_bounds__(512, 1)
void gemm_h_kernel(const float* __restrict__ x, const float* __restrict__ W)
{
    extern __shared__ float sm[];
    const uint32_t sb = smem_u32(sm);

    const int t    = threadIdx.x;
    const int m0   = blockIdx.x * 128;
    const int warp = t >> 5, lane = t & 31;
    const int g    = lane >> 2, tig = lane & 3;
    const int wi   = warp >> 2, wo = warp & 3;

    const int xrow = t >> 2, xseg = (t & 3) * 4;
    const int wrow = t >> 5, wseg = (t & 31) * 8;
    const float* xsrc = x + (size_t)(m0 + xrow) * FIN + xseg;
    const float* wsrc = W + (size_t)wrow * FOUT + wseg;

    auto issue = [&](int s) {
        uint32_t xd = sb + (XS_OFF + (s & 1) * XS_SZ + xrow * 20 + xseg) * 4;
        cp16(xd, xsrc + s * 16);
        uint32_t wd = sb + (WS_OFF + (s & 1) * WS_SZ + wrow * 264 + wseg) * 4;
        cp16(wd,      wsrc + (size_t)s * 16 * FOUT);
        cp16(wd + 16, wsrc + (size_t)s * 16 * FOUT + 4);
        CP_COMMIT();
    };

    float acc[2][8][4];
    #pragma unroll
    for (int ma = 0; ma < 2; ma++)
        #pragma unroll
        for (int na = 0; na < 8; na++)
            #pragma unroll
            for (int c = 0; c < 4; c++) acc[ma][na][c] = 0.f;

    issue(0);
    CP_WAIT0();
    __syncthreads();

    for (int s = 0; s < 32; s++) {
        if (s < 31) issue(s + 1);
        const float* xs = sm + XS_OFF + (s & 1) * XS_SZ;
        const float* ws = sm + WS_OFF + (s & 1) * WS_SZ;

        #pragma unroll
        for (int ks = 0; ks < 2; ks++) {
            uint32_t bhi[8][2];
            #pragma unroll
            for (int na = 0; na < 8; na++) {
                int o = wo * 64 + na * 8 + g;
                bhi[na][0] = to_tf32(ws[(ks * 8 + tig) * 264 + o]);
                bhi[na][1] = to_tf32(ws[(ks * 8 + tig + 4) * 264 + o]);
            }
            #pragma unroll
            for (int ma = 0; ma < 2; ma++) {
                int R = wi * 32 + ma * 16;
                uint32_t ahi[4];
                ahi[0] = to_tf32(xs[(R + g) * 20 + ks * 8 + tig]);
                ahi[1] = to_tf32(xs[(R + g + 8) * 20 + ks * 8 + tig]);
                ahi[2] = to_tf32(xs[(R + g) * 20 + ks * 8 + tig + 4]);
                ahi[3] = to_tf32(xs[(R + g + 8) * 20 + ks * 8 + tig + 4]);
                #pragma unroll
                for (int na = 0; na < 8; na++)
                    mma_tf32(acc[ma][na], ahi, bhi[na]);
            }
        }
        if (s < 31) CP_WAIT0();
        __syncthreads();
    }

    #pragma unroll
    for (int ma = 0; ma < 2; ma++) {
        int ra = wi * 32 + ma * 16 + g;
        int rb = ra + 8;
        #pragma unroll
        for (int na = 0; na < 8; na++) {
            int col = wo * 64 + na * 8 + tig * 2;
            float2 sA = make_float2(__uint_as_float(to_tf32(acc[ma][na][0])),
                                    __uint_as_float(to_tf32(acc[ma][na][1])));
            float2 sB = make_float2(__uint_as_float(to_tf32(acc[ma][na][2])),
                                    __uint_as_float(to_tf32(acc[ma][na][3])));
            *(float2*)(g_h + (size_t)(m0 + ra) * FOUT + col) = sA;
            *(float2*)(g_h + (size_t)(m0 + rb) * FOUT + col) = sB;
        }
    }
}

// ===========================================================================
// Kernel 3: attention (R11 verbatim — proven 166.8us).
// 1024 threads, warp grid 4(i) x 8(o), j-tile 32, double-buffered.
// ===========================================================================
#define AT_DSUM 0
#define AT_GS   1024
#define AT_PS0  3072
#define AT_PS1  7680
#define AT_HS0  12288
#define AT_HS1  20736
#define AT_HS_SZ 8448
#define ATTN_SMEM (29184 * 4)

__global__ __launch_bounds__(1024, 1)
void attn_kernel(const int* __restrict__ adj, float* __restrict__ out)
{
    extern __shared__ float smf[];
    const uint32_t sb = smem_u32(smf);

    const int t    = threadIdx.x;
    const int b    = blockIdx.x >> 4;
    const int i0   = (blockIdx.x & 15) << 7;
    const int warp = t >> 5, lane = t & 31;
    const int g    = lane >> 2, tig = lane & 3;
    const int wiq  = warp >> 3, wo = warp & 7;

    const int irow = t >> 3;
    const int jq   = t & 7;
    const int hjr  = t >> 5;
    const int hoc  = (t & 31) * 8;

    for (int j = t; j < NN; j += 1024) smf[AT_GS + j] = g_g[b * NN + j];
    const float fv = g_f[b * NN + i0 + irow];
    const int*   adjrow = adj + ((size_t)b * NN + i0 + irow) * NN + jq * 4;
    const float* hb     = g_h + (size_t)b * NN * FOUT;

    float acc[2][4][4];
    #pragma unroll
    for (int ma = 0; ma < 2; ma++)
        #pragma unroll
        for (int na = 0; na < 4; na++)
            #pragma unroll
            for (int c = 0; c < 4; c++) acc[ma][na][c] = 0.f;
    float dloc = 0.f;

    auto cp_h = [&](int jt) {
        const float* src = hb + (size_t)(jt * 32 + hjr) * FOUT + hoc;
        uint32_t dst = sb + (AT_HS0 + (jt & 1) * AT_HS_SZ + hjr * 264 + hoc) * 4;
        cp16(dst,      src);
        cp16(dst + 16, src + 4);
        CP_COMMIT();
    };
    auto ld_adj = [&](int jtp, int4& av) {
        av = *(const int4*)(adjrow + jtp * 32);
    };
    auto store_p = [&](int jtp, const int4& v) {
        float* ps = smf + (jtp & 1 ? AT_PS1 : AT_PS0);
        const float* gsr = smf + AT_GS + jtp * 32 + jq * 4;
        float z0 = fv + gsr[0]; z0 = z0 >= 0.f ? z0 : 0.2f * z0;
        float z1 = fv + gsr[1]; z1 = z1 >= 0.f ? z1 : 0.2f * z1;
        float z2 = fv + gsr[2]; z2 = z2 >= 0.f ? z2 : 0.2f * z2;
        float z3 = fv + gsr[3]; z3 = z3 >= 0.f ? z3 : 0.2f * z3;
        float p0 = (v.x > 0) ? __expf(z0) : 0.f;
        float p1 = (v.y > 0) ? __expf(z1) : 0.f;
        float p2 = (v.z > 0) ? __expf(z2) : 0.f;
        float p3 = (v.w > 0) ? __expf(z3) : 0.f;
        dloc += p0 + p1 + p2 + p3;
        float4 st = make_float4(__uint_as_float(to_tf32(p0)),
                                __uint_as_float(to_tf32(p1)),
                                __uint_as_float(to_tf32(p2)),
                                __uint_as_float(to_tf32(p3)));
        *(float4*)(ps + irow * 36 + jq * 4) = st;
    };
    auto do_mma = [&](int jt) {
        const uint32_t* psu = (const uint32_t*)(smf + (jt & 1 ? AT_PS1 : AT_PS0));
        const uint32_t* hsu = (const uint32_t*)(smf + (jt & 1 ? AT_HS1 : AT_HS0));
        #pragma unroll
        for (int ks = 0; ks < 4; ks++) {
            uint32_t afr[2][4];
            #pragma unroll
            for (int ma = 0; ma < 2; ma++) {
                int base = (wiq * 32 + ma * 16 + g) * 36 + ks * 8 + tig;
                afr[ma][0] = psu[base];
                afr[ma][1] = psu[base + 8 * 36];
                afr[ma][2] = psu[base + 4];
                afr[ma][3] = psu[base + 8 * 36 + 4];
            }
            uint32_t bfr[4][2];
            #pragma unroll
            for (int na = 0; na < 4; na++) {
                int o = wo * 32 + na * 8 + g;
                bfr[na][0] = hsu[(ks * 8 + tig) * 264 + o];
                bfr[na][1] = hsu[(ks * 8 + tig + 4) * 264 + o];
            }
            #pragma unroll
            for (int ma = 0; ma < 2; ma++)
                #pragma unroll
                for (int na = 0; na < 4; na++)
                    mma_tf32(acc[ma][na], afr[ma], bfr[na]);
        }
    };

    int4 A0, A1;
    cp_h(0);
    ld_adj(0, A0);
    ld_adj(1, A1);
    CP_WAIT0();
    __syncthreads();
    store_p(0, A0);
    ld_adj(2, A0);
    __syncthreads();

    for (int jt = 0; jt < 64; jt += 2) {
        {
            if (jt < 63) cp_h(jt + 1);
            do_mma(jt);
            if (jt < 63) store_p(jt + 1, A1);
            if (jt + 3 < 64) ld_adj(jt + 3, A1);
            if (jt < 63) CP_WAIT0();
            __syncthreads();
        }
        {
            int jo = jt + 1;
            if (jo < 63) cp_h(jo + 1);
            do_mma(jo);
            if (jo < 63) store_p(jo + 1, A0);
            if (jo + 3 < 64) ld_adj(jo + 3, A0);
            if (jo < 63) CP_WAIT0();
            __syncthreads();
        }
    }

    smf[AT_DSUM + jq * 128 + irow] = dloc;
    __syncthreads();

    #pragma unroll
    for (int ma = 0; ma < 2; ma++) {
        int ra = wiq * 32 + ma * 16 + g;
        int rb = ra + 8;
        float da = 0.f, db = 0.f;
        #pragma unroll
        for (int s = 0; s < 8; s++) {
            da += smf[AT_DSUM + s * 128 + ra];
            db += smf[AT_DSUM + s * 128 + rb];
        }
        float inva = (da > 0.f) ? 1.f / da : 0.f;
        float invb = (db > 0.f) ? 1.f / db : 0.f;
        float* outa = out + ((size_t)b * NN + i0 + ra) * FOUT;
        float* outb = out + ((size_t)b * NN + i0 + rb) * FOUT;
        #pragma unroll
        for (int na = 0; na < 4; na++) {
            int col = wo * 32 + na * 8 + tig * 2;
            float v0 = acc[ma][na][0] * inva;
            float v1 = acc[ma][na][1] * inva;
            float v2 = acc[ma][na][2] * invb;
            float v3 = acc[ma][na][3] * invb;
            v0 = v0 > 0.f ? v0 : expm1f(v0);
            v1 = v1 > 0.f ? v1 : expm1f(v1);
            v2 = v2 > 0.f ? v2 : expm1f(v2);
            v3 = v3 > 0.f ? v3 : expm1f(v3);
            *(float2*)(outa + col) = make_float2(v0, v1);
            *(float2*)(outb + col) = make_float2(v2, v3);
        }
    }
}

// ---------------------------------------------------------------------------
extern "C" void kernel_launch(void* const* d_in, const int* in_sizes, int n_in,
                              void* d_out, int out_size)
{
    const float* x   = (const float*)d_in[0];
    const int*   adj = (const int*)d_in[1];
    const float* W   = (const float*)d_in[2];
    const float* a   = (const float*)d_in[3];
    float*       out = (float*)d_out;

    cudaFuncSetAttribute(gemm_h_kernel, cudaFuncAttributeMaxDynamicSharedMemorySize, GH_SMEM);
    cudaFuncSetAttribute(attn_kernel,   cudaFuncAttributeMaxDynamicSharedMemorySize, ATTN_SMEM);

    wv_kernel<<<64, 256>>>(W, a);
    gemm_h_kernel<<<128, 512, GH_SMEM>>>(x, W);
    fg_kernel<<<2048, 256>>>(x);
    attn_kernel<<<128, 1024, ATTN_SMEM>>>(adj, out);
}